// round 15
// baseline (speedup 1.0000x reference)
#include <cuda_runtime.h>

#define NC    6
#define CF    64
#define Hh    88
#define Ww    160
#define HWp   (Hh*Ww)          // 14080
#define XD    100
#define YD    100
#define ZD    20
#define NVOX  (XD*YD*ZD)       // 200000

// scratch
__device__ float  g_featT[NC * HWp * CF];   // channel-last features [cam][H][W][C]
__device__ float4 g_q1[NVOX * 2];           // count==1: {n,meta,w0,w1},{w2,w3,z,0}
__device__ float4 g_q2[NVOX * 4];           // count==2: {n,metaA,metaB,0},{wA},{wB},{z0,z1,0,0}
__device__ int    g_cnt[2];
__device__ float2 g_w1p[65 * 32];           // packed w_no: [k][lane]={W[l][k],W[l+32][k]}
__device__ float2 g_w2p[130 * 32];          // packed w_o
__device__ unsigned char g_flag[NVOX];      // 1 = active (count 1 or 2)

__device__ __forceinline__ float elu1(float x) { return x > 0.f ? x : expm1f(x); }

// pack + counter reset (classify follows in stream order -> reset is safe)
__global__ void pack_kernel(const float* __restrict__ w_no, const float* __restrict__ w_o) {
    int i = blockIdx.x * 256 + threadIdx.x;
    if (i < 2) g_cnt[i] = 0;
    if (i < 65 * 32) {
        int k = i >> 5, l = i & 31;
        g_w1p[i] = make_float2(w_no[l * 65 + k], w_no[(l + 32) * 65 + k]);
    }
    if (i < 130 * 32) {
        int k = i >> 5, l = i & 31;
        g_w2p[i] = make_float2(w_o[l * 130 + k], w_o[(l + 32) * 130 + k]);
    }
}

__global__ void transpose_kernel(const float* __restrict__ feat) {
    __shared__ float tile[32][33];
    int cam = blockIdx.z;
    int c0  = blockIdx.y * 32;
    int p0  = blockIdx.x * 32;
    int tx = threadIdx.x, ty = threadIdx.y;
    const float* src = feat + (size_t)cam * CF * HWp;
#pragma unroll
    for (int i = ty; i < 32; i += 8)
        tile[i][tx] = src[(c0 + i) * HWp + p0 + tx];
    __syncthreads();
    float* dst = g_featT + (size_t)cam * HWp * CF;
#pragma unroll
    for (int i = ty; i < 32; i += 8)
        dst[(p0 + i) * CF + c0 + tx] = tile[tx][i];
}

__global__ __launch_bounds__(256) void classify_kernel(
    const float* __restrict__ mask,
    const float* __restrict__ Kin,
    const float* __restrict__ Ein)
{
    __shared__ float sE[96], sK[96];
    __shared__ int sh_cnt[2], sh_base[2];
    int tid = threadIdx.x;
    if (tid < 96) { sE[tid] = Ein[tid]; sK[tid] = Kin[tid]; }
    if (tid < 2) sh_cnt[tid] = 0;
    __syncthreads();

    int n = blockIdx.x * 256 + tid;
    int count = 0;
    int metaA = 0, metaB = 0;
    float wA0 = 0.f, wA1 = 0.f, wA2 = 0.f, wA3 = 0.f;
    float wB0 = 0.f, wB1 = 0.f, wB2 = 0.f, wB3 = 0.f;
    float z0 = 0.f, z1 = 0.f;
    if (n < NVOX) {
        int x = n % XD, y = (n / XD) % YD, z = n / (XD * YD);
        float X = -50.f + (float)x;
        float Y = -50.f + (float)y;
        float Z = -15.f + 1.5f * (float)z;
#pragma unroll
        for (int cam = 0; cam < NC; cam++) {
            const float* E  = sE + cam * 16;
            const float* Km = sK + cam * 16;
            float vx = E[0] * X + E[1] * Y + E[2]  * Z + E[3];
            float vy = E[4] * X + E[5] * Y + E[6]  * Z + E[7];
            float vz = E[8] * X + E[9] * Y + E[10] * Z + E[11];
            if (!(vz > 0.f)) continue;
            float cx = Km[0] * vx + Km[1] * vy + Km[2]  * vz;
            float cy = Km[4] * vx + Km[5] * vy + Km[6]  * vz;
            float cz = Km[8] * vx + Km[9] * vy + Km[10] * vz;
            float denom = cz + 1e-8f;
            // ---- fast reject (safe margin >= 1 pixel; NaN/inf fall through) ----
            float rcp = __frcp_rn(denom);
            float pxa = cx * rcp, pya = cy * rcp;
            if (pxa < -1.f || pxa > 160.f || pya < -1.f || pya > 88.f) continue;
            // ---- exact path (bit-identical to reference) ----
            float px = __fdiv_rn(cx, denom);
            float py = __fdiv_rn(cy, denom);
            float gx = (__fdiv_rn(px, 159.f) - 0.5f) * 2.f;
            float gy = (__fdiv_rn(py,  87.f) - 0.5f) * 2.f;
            if (gx > 1.f || gx < -1.f || gy > 1.f || gy < -1.f) continue;
            float xs = (gx + 1.f) * 0.5f * 159.f;
            float ys = (gy + 1.f) * 0.5f * 87.f;
            float xr = rintf(xs), yr = rintf(ys);
            if (!(xr >= 0.f && xr <= 159.f && yr >= 0.f && yr <= 87.f)) continue;
            float mv = __ldg(mask + cam * HWp + (int)yr * Ww + (int)xr);
            if (!(mv > 0.5f)) continue;
            // ---- precompute bilinear coeffs (reference-exact weights & clipping) ----
            float x0f = floorf(xs), y0f = floorf(ys);
            float wx1 = xs - x0f, wx0 = 1.f - wx1;
            float wy1 = ys - y0f, wy0 = 1.f - wy1;
            int x0 = (int)x0f, y0 = (int)y0f;           // in [0,159] / [0,87]
            bool vx1 = (x0 + 1 <= 159), vy1 = (y0 + 1 <= 87);
            // corner order matches gather: (x0,y0),(x0+1,y0),(x0,y0+1),(x0+1,y0+1)
            float cw0 = wx0 * wy0;
            float cw1 = vx1 ? (wx1 * wy0) : 0.f;
            float cw2 = vy1 ? (wx0 * wy1) : 0.f;
            float cw3 = (vx1 && vy1) ? (wx1 * wy1) : 0.f;
            int dx = vx1 ? 1 : 0, dy = vy1 ? 1 : 0;
            int meta = (y0 * Ww + x0) | (dx << 14) | (dy << 15) | (cam << 16);
            if (count == 0) { metaA = meta; wA0 = cw0; wA1 = cw1; wA2 = cw2; wA3 = cw3; }
            else if (count == 1) { metaB = meta; wB0 = cw0; wB1 = cw1; wB2 = cw2; wB3 = cw3; }
            count++;
            float dz = __fdiv_rn(vz, 100.f);
            if (cam == 0 || cam == 3 || cam == 4) z0 += dz; else z1 += dz;
        }
    }
    int lane = tid & 31;
    unsigned lt = (1u << lane) - 1u;
    unsigned m1 = __ballot_sync(0xFFFFFFFFu, count == 1);
    unsigned m2 = __ballot_sync(0xFFFFFFFFu, count == 2);
    int w1 = 0, w2o = 0;
    if (m1) {
        int ldr = __ffs(m1) - 1;
        if (lane == ldr) w1 = atomicAdd(&sh_cnt[0], __popc(m1));
        w1 = __shfl_sync(0xFFFFFFFFu, w1, ldr);
    }
    if (m2) {
        int ldr = __ffs(m2) - 1;
        if (lane == ldr) w2o = atomicAdd(&sh_cnt[1], __popc(m2));
        w2o = __shfl_sync(0xFFFFFFFFu, w2o, ldr);
    }
    __syncthreads();
    if (tid < 2) sh_base[tid] = atomicAdd(&g_cnt[tid], sh_cnt[tid]);
    __syncthreads();
    if (n < NVOX) {
        g_flag[n] = (count == 1 || count == 2) ? 1 : 0;
        if (count == 1) {
            int idx = sh_base[0] + w1 + __popc(m1 & lt);
            g_q1[idx * 2]     = make_float4(__int_as_float(n), __int_as_float(metaA), wA0, wA1);
            g_q1[idx * 2 + 1] = make_float4(wA2, wA3, z0 + z1, 0.f);
        } else if (count == 2) {
            int idx = sh_base[1] + w2o + __popc(m2 & lt);
            g_q2[idx * 4]     = make_float4(__int_as_float(n), __int_as_float(metaA), __int_as_float(metaB), 0.f);
            g_q2[idx * 4 + 1] = make_float4(wA0, wA1, wA2, wA3);
            g_q2[idx * 4 + 2] = make_float4(wB0, wB1, wB2, wB3);
            g_q2[idx * 4 + 3] = make_float4(z0, z1, 0.f, 0.f);
        }
    }
}

// gather with precomputed coeffs: 4 clipped-address loads + FMA chain
// (same accumulation order as the previous bilin -> identical rounding)
__device__ __forceinline__ float2 bilin_pre(int meta, float w0, float w1, float w2, float w3, int lane) {
    int a00 = meta & 0x3FFF;
    int dx  = (meta >> 14) & 1;
    int dy  = (meta >> 15) & 1;
    int cam = meta >> 16;
    const float2* base = (const float2*)(g_featT + (size_t)cam * HWp * CF) + lane;
    float2 v00 = __ldg(base + a00 * 32);
    float2 v01 = __ldg(base + (a00 + dx) * 32);
    float2 v10 = __ldg(base + (a00 + dy * Ww) * 32);
    float2 v11 = __ldg(base + (a00 + dy * Ww + dx) * 32);
    float ax = w0 * v00.x;  float ay = w0 * v00.y;
    ax = fmaf(w1, v01.x, ax); ay = fmaf(w1, v01.y, ay);
    ax = fmaf(w2, v10.x, ax); ay = fmaf(w2, v10.y, ay);
    ax = fmaf(w3, v11.x, ax); ay = fmaf(w3, v11.y, ay);
    return make_float2(ax, ay);
}

// body shared by gemm65 and combo: stage weights once, grid-stride over tiles.
template<int KR, int QIDX>
__device__ __forceinline__ void gemm_tiles(float* smem, const float* __restrict__ bias,
                                           float* __restrict__ out, int total)
{
    float2* w2  = (float2*)smem;                 // [KR][32]
    float*  fsm = smem + KR * 64;                // [KR][68] feats / sout alias
    float*  sb  = fsm + KR * 68;                 // [64]
    int*    s_n = (int*)(sb + 64);               // [64]

    int tid = threadIdx.x, lane = tid & 31, warp = tid >> 5;
    const float2* Wp = QIDX ? g_w2p : g_w1p;
    for (int i = tid; i < KR * 32; i += 256)     // coalesced packed copy
        w2[i] = __ldg(Wp + i);
    if (tid < 64) sb[tid] = bias[tid];

    for (int tile = blockIdx.x; tile * 64 < total; tile += gridDim.x) {
        __syncthreads();
        // ---- gather ----
        if (QIDX == 0) {
#pragma unroll
            for (int jb = 0; jb < 2; jb++) {
                float4 ra[4], rb[4];
#pragma unroll
                for (int u = 0; u < 4; u++) {
                    int r = tile * 64 + warp * 8 + jb * 4 + u;
                    if (r < total) {
                        ra[u] = __ldg(g_q1 + r * 2);
                        rb[u] = __ldg(g_q1 + r * 2 + 1);
                    } else {
                        ra[u] = make_float4(__int_as_float(-1), 0.f, 0.f, 0.f);
                        rb[u] = make_float4(0.f, 0.f, 0.f, 0.f);
                    }
                }
#pragma unroll
                for (int u = 0; u < 4; u++) {
                    int v = warp * 8 + jb * 4 + u;
                    int n = __float_as_int(ra[u].x);
                    if (n >= 0) {
                        float2 a = bilin_pre(__float_as_int(ra[u].y),
                                             ra[u].z, ra[u].w, rb[u].x, rb[u].y, lane);
                        fsm[(2 * lane) * 68 + v]     = a.x;
                        fsm[(2 * lane + 1) * 68 + v] = a.y;
                        if (lane == 0) { fsm[64 * 68 + v] = rb[u].z; s_n[v] = n; }
                    } else if (lane == 0) s_n[v] = -1;
                }
            }
        } else {
#pragma unroll
            for (int jb = 0; jb < 4; jb++) {
                float4 ra[2], rwa[2], rwb[2], rz[2];
#pragma unroll
                for (int u = 0; u < 2; u++) {
                    int r = tile * 64 + warp * 8 + jb * 2 + u;
                    if (r < total) {
                        ra[u]  = __ldg(g_q2 + r * 4);
                        rwa[u] = __ldg(g_q2 + r * 4 + 1);
                        rwb[u] = __ldg(g_q2 + r * 4 + 2);
                        rz[u]  = __ldg(g_q2 + r * 4 + 3);
                    } else {
                        ra[u] = make_float4(__int_as_float(-1), 0.f, 0.f, 0.f);
                        rwa[u] = rwb[u] = rz[u] = make_float4(0.f, 0.f, 0.f, 0.f);
                    }
                }
#pragma unroll
                for (int u = 0; u < 2; u++) {
                    int v = warp * 8 + jb * 2 + u;
                    int n = __float_as_int(ra[u].x);
                    if (n >= 0) {
                        int metaA = __float_as_int(ra[u].y);
                        int metaB = __float_as_int(ra[u].z);
                        int camA = metaA >> 16, camB = metaB >> 16;
                        float2 a = bilin_pre(metaA, rwa[u].x, rwa[u].y, rwa[u].z, rwa[u].w, lane);
                        float2 b = bilin_pre(metaB, rwb[u].x, rwb[u].y, rwb[u].z, rwb[u].w, lane);
                        float2 h0 = make_float2(0.f, 0.f), h1 = make_float2(0.f, 0.f);
                        if (camA == 0 || camA == 3 || camA == 4) { h0.x += a.x; h0.y += a.y; }
                        else                                     { h1.x += a.x; h1.y += a.y; }
                        if (camB == 0 || camB == 3 || camB == 4) { h0.x += b.x; h0.y += b.y; }
                        else                                     { h1.x += b.x; h1.y += b.y; }
                        fsm[(2 * lane) * 68 + v]          = h0.x;
                        fsm[(2 * lane + 1) * 68 + v]      = h0.y;
                        fsm[(65 + 2 * lane) * 68 + v]     = h1.x;
                        fsm[(65 + 2 * lane + 1) * 68 + v] = h1.y;
                        if (lane == 0) { fsm[64 * 68 + v] = rz[u].x; fsm[129 * 68 + v] = rz[u].y; s_n[v] = n; }
                    } else if (lane == 0) s_n[v] = -1;
                }
            }
        }
        __syncthreads();
        // ---- GEMM ----
        float acc[16];
#pragma unroll
        for (int i = 0; i < 16; i++) acc[i] = 0.f;
        int vb = warp * 8;
#pragma unroll 5
        for (int k = 0; k < KR; k++) {
            float2 wv = w2[k * 32 + lane];
            float4 f0 = *(const float4*)(fsm + k * 68 + vb);
            float4 f1 = *(const float4*)(fsm + k * 68 + vb + 4);
            acc[0]  = fmaf(wv.x, f0.x, acc[0]);  acc[1]  = fmaf(wv.y, f0.x, acc[1]);
            acc[2]  = fmaf(wv.x, f0.y, acc[2]);  acc[3]  = fmaf(wv.y, f0.y, acc[3]);
            acc[4]  = fmaf(wv.x, f0.z, acc[4]);  acc[5]  = fmaf(wv.y, f0.z, acc[5]);
            acc[6]  = fmaf(wv.x, f0.w, acc[6]);  acc[7]  = fmaf(wv.y, f0.w, acc[7]);
            acc[8]  = fmaf(wv.x, f1.x, acc[8]);  acc[9]  = fmaf(wv.y, f1.x, acc[9]);
            acc[10] = fmaf(wv.x, f1.y, acc[10]); acc[11] = fmaf(wv.y, f1.y, acc[11]);
            acc[12] = fmaf(wv.x, f1.z, acc[12]); acc[13] = fmaf(wv.y, f1.z, acc[13]);
            acc[14] = fmaf(wv.x, f1.w, acc[14]); acc[15] = fmaf(wv.y, f1.w, acc[15]);
        }
        __syncthreads();
        float* som = fsm;
        float b0 = sb[lane], b1 = sb[lane + 32];
#pragma unroll
        for (int j = 0; j < 8; j++) {
            som[lane * 65 + vb + j]        = elu1(acc[2 * j]     + b0);
            som[(lane + 32) * 65 + vb + j] = elu1(acc[2 * j + 1] + b1);
        }
        __syncthreads();
#pragma unroll
        for (int i = tid; i < 64 * 64; i += 256) {
            int o = i >> 6, v = i & 63;
            int nn = s_n[v];
            if (nn >= 0) out[(size_t)o * NVOX + nn] = som[o * 65 + v];
        }
    }
}

__global__ __launch_bounds__(256, 4) void gemm65_kernel(
    const float* __restrict__ bias, float* __restrict__ out)
{
    extern __shared__ float smem[];
    int total = g_cnt[0];
    if (blockIdx.x * 64 >= total) return;
    gemm_tiles<65, 0>(smem, bias, out, total);
}

// combo: q2 GEMM tiles + zero-fill of inactive columns, one launch
__global__ __launch_bounds__(256) void combo_kernel(
    const float* __restrict__ bias, float* __restrict__ out)
{
    extern __shared__ float smem[];
    int total = g_cnt[1];
    if (blockIdx.x * 64 < total)
        gemm_tiles<130, 1>(smem, bias, out, total);
    // fill: every block handles one 256-voxel chunk
    int n = blockIdx.x * 256 + threadIdx.x;
    if (n < NVOX && !g_flag[n]) {
#pragma unroll
        for (int o = 0; o < 64; o++) out[(size_t)o * NVOX + n] = 0.f;
    }
}

extern "C" void kernel_launch(void* const* d_in, const int* in_sizes, int n_in,
                              void* d_out, int out_size) {
    const float* feat = (const float*)d_in[0];
    const float* mask = (const float*)d_in[1];
    const float* K    = (const float*)d_in[2];
    const float* ext  = (const float*)d_in[3];
    const float* w_no = (const float*)d_in[4];
    const float* b_no = (const float*)d_in[5];
    const float* w_o  = (const float*)d_in[6];
    const float* b_o  = (const float*)d_in[7];
    float* out = (float*)d_out;

    static cudaStream_t s1 = nullptr;
    static cudaEvent_t e0 = nullptr, e_t = nullptr, e_c = nullptr, e_f = nullptr;
    if (!s1) {
        cudaStreamCreateWithFlags(&s1, cudaStreamNonBlocking);
        cudaEventCreateWithFlags(&e0,  cudaEventDisableTiming);
        cudaEventCreateWithFlags(&e_t, cudaEventDisableTiming);
        cudaEventCreateWithFlags(&e_c, cudaEventDisableTiming);
        cudaEventCreateWithFlags(&e_f, cudaEventDisableTiming);
    }

    const int smem1 = (65 * 64  + 65 * 68  + 64 + 64) * 4;   // 34832
    const int smem2 = (130 * 64 + 130 * 68 + 64 + 64) * 4;   // 69152
    cudaFuncSetAttribute(gemm65_kernel, cudaFuncAttributeMaxDynamicSharedMemorySize, smem1);
    cudaFuncSetAttribute(combo_kernel,  cudaFuncAttributeMaxDynamicSharedMemorySize, smem2);

    // s0: pack(+cnt reset) -> classify -> [e_t] -> gemm65
    // s1: transpose -> [e_c] -> combo (q2 gemm + fill)
    cudaEventRecord(e0, 0);
    cudaStreamWaitEvent(s1, e0, 0);

    dim3 tg(HWp / 32, CF / 32, NC);   // 440 x 2 x 6
    transpose_kernel<<<tg, dim3(32, 8), 0, s1>>>(feat);
    cudaEventRecord(e_t, s1);

    pack_kernel<<<17, 256>>>(w_no, w_o);
    classify_kernel<<<(NVOX + 255) / 256, 256>>>(mask, K, ext);
    cudaEventRecord(e_c, 0);

    cudaStreamWaitEvent(0, e_t, 0);
    gemm65_kernel<<<888, 256, smem1, 0>>>(b_no, out);

    cudaStreamWaitEvent(s1, e_c, 0);
    combo_kernel<<<(NVOX + 255) / 256, 256, smem2, s1>>>(b_o, out);
    cudaEventRecord(e_f, s1);

    cudaStreamWaitEvent(0, e_f, 0);
}

// round 16
// speedup vs baseline: 1.5032x; 1.5032x over previous
#include <cuda_runtime.h>

#define NC    6
#define CF    64
#define Hh    88
#define Ww    160
#define HWp   (Hh*Ww)          // 14080
#define XD    100
#define YD    100
#define ZD    20
#define NVOX  (XD*YD*ZD)       // 200000

// scratch
__device__ float  g_featT[NC * HWp * CF];   // channel-last features [cam][H][W][C]
__device__ float4 g_q1[NVOX * 2];           // count==1 records
__device__ float4 g_q2[NVOX * 2];           // count==2 records
__device__ int    g_cnt[2];
__device__ float2 g_w1p[65 * 32];           // packed w_no: [k][lane]={W[l][k],W[l+32][k]}
__device__ float2 g_w2p[130 * 32];          // packed w_o
__device__ unsigned char g_flag[NVOX];      // 1 = active (count 1 or 2)

__device__ __forceinline__ float elu1(float x) { return x > 0.f ? x : expm1f(x); }

// pack + counter reset (classify follows in stream order -> reset is safe)
__global__ void pack_kernel(const float* __restrict__ w_no, const float* __restrict__ w_o) {
    int i = blockIdx.x * 256 + threadIdx.x;
    if (i < 2) g_cnt[i] = 0;
    if (i < 65 * 32) {
        int k = i >> 5, l = i & 31;
        g_w1p[i] = make_float2(w_no[l * 65 + k], w_no[(l + 32) * 65 + k]);
    }
    if (i < 130 * 32) {
        int k = i >> 5, l = i & 31;
        g_w2p[i] = make_float2(w_o[l * 130 + k], w_o[(l + 32) * 130 + k]);
    }
}

__global__ void transpose_kernel(const float* __restrict__ feat) {
    __shared__ float tile[32][33];
    int cam = blockIdx.z;
    int c0  = blockIdx.y * 32;
    int p0  = blockIdx.x * 32;
    int tx = threadIdx.x, ty = threadIdx.y;
    const float* src = feat + (size_t)cam * CF * HWp;
#pragma unroll
    for (int i = ty; i < 32; i += 8)
        tile[i][tx] = src[(c0 + i) * HWp + p0 + tx];
    __syncthreads();
    float* dst = g_featT + (size_t)cam * HWp * CF;
#pragma unroll
    for (int i = ty; i < 32; i += 8)
        dst[(p0 + i) * CF + c0 + tx] = tile[tx][i];
}

__global__ __launch_bounds__(256) void classify_kernel(
    const float* __restrict__ mask,
    const float* __restrict__ Kin,
    const float* __restrict__ Ein)
{
    __shared__ float sE[96], sK[96];
    __shared__ int sh_cnt[2], sh_base[2];
    int tid = threadIdx.x;
    if (tid < 96) { sE[tid] = Ein[tid]; sK[tid] = Kin[tid]; }
    if (tid < 2) sh_cnt[tid] = 0;
    __syncthreads();

    int n = blockIdx.x * 256 + tid;
    int count = 0, camA = 0, camB = 0;
    float xsA = 0.f, ysA = 0.f, xsB = 0.f, ysB = 0.f, z0 = 0.f, z1 = 0.f;
    if (n < NVOX) {
        int x = n % XD, y = (n / XD) % YD, z = n / (XD * YD);
        float X = -50.f + (float)x;
        float Y = -50.f + (float)y;
        float Z = -15.f + 1.5f * (float)z;
#pragma unroll
        for (int cam = 0; cam < NC; cam++) {
            const float* E  = sE + cam * 16;
            const float* Km = sK + cam * 16;
            float vx = E[0] * X + E[1] * Y + E[2]  * Z + E[3];
            float vy = E[4] * X + E[5] * Y + E[6]  * Z + E[7];
            float vz = E[8] * X + E[9] * Y + E[10] * Z + E[11];
            if (!(vz > 0.f)) continue;
            float cx = Km[0] * vx + Km[1] * vy + Km[2]  * vz;
            float cy = Km[4] * vx + Km[5] * vy + Km[6]  * vz;
            float cz = Km[8] * vx + Km[9] * vy + Km[10] * vz;
            float denom = cz + 1e-8f;
            // ---- fast reject (safe margin >= 1 pixel; NaN/inf fall through) ----
            float rcp = __frcp_rn(denom);
            float pxa = cx * rcp, pya = cy * rcp;
            if (pxa < -1.f || pxa > 160.f || pya < -1.f || pya > 88.f) continue;
            // ---- exact path (bit-identical to reference) ----
            float px = __fdiv_rn(cx, denom);
            float py = __fdiv_rn(cy, denom);
            float gx = (__fdiv_rn(px, 159.f) - 0.5f) * 2.f;
            float gy = (__fdiv_rn(py,  87.f) - 0.5f) * 2.f;
            if (gx > 1.f || gx < -1.f || gy > 1.f || gy < -1.f) continue;
            float xs = (gx + 1.f) * 0.5f * 159.f;
            float ys = (gy + 1.f) * 0.5f * 87.f;
            float xr = rintf(xs), yr = rintf(ys);
            if (!(xr >= 0.f && xr <= 159.f && yr >= 0.f && yr <= 87.f)) continue;
            float mv = __ldg(mask + cam * HWp + (int)yr * Ww + (int)xr);
            if (!(mv > 0.5f)) continue;
            if (count == 0)      { camA = cam; xsA = xs; ysA = ys; }
            else if (count == 1) { camB = cam; xsB = xs; ysB = ys; }
            count++;
            float dz = __fdiv_rn(vz, 100.f);
            if (cam == 0 || cam == 3 || cam == 4) z0 += dz; else z1 += dz;
        }
    }
    int lane = tid & 31;
    unsigned lt = (1u << lane) - 1u;
    unsigned m1 = __ballot_sync(0xFFFFFFFFu, count == 1);
    unsigned m2 = __ballot_sync(0xFFFFFFFFu, count == 2);
    int w1 = 0, w2o = 0;
    if (m1) {
        int ldr = __ffs(m1) - 1;
        if (lane == ldr) w1 = atomicAdd(&sh_cnt[0], __popc(m1));
        w1 = __shfl_sync(0xFFFFFFFFu, w1, ldr);
    }
    if (m2) {
        int ldr = __ffs(m2) - 1;
        if (lane == ldr) w2o = atomicAdd(&sh_cnt[1], __popc(m2));
        w2o = __shfl_sync(0xFFFFFFFFu, w2o, ldr);
    }
    __syncthreads();
    if (tid < 2) sh_base[tid] = atomicAdd(&g_cnt[tid], sh_cnt[tid]);
    __syncthreads();
    if (n < NVOX) {
        g_flag[n] = (count == 1 || count == 2) ? 1 : 0;
        if (count == 1) {
            int idx = sh_base[0] + w1 + __popc(m1 & lt);
            g_q1[idx * 2]     = make_float4(__int_as_float(n), __int_as_float(camA), xsA, ysA);
            g_q1[idx * 2 + 1] = make_float4(z0 + z1, 0.f, 0.f, 0.f);
        } else if (count == 2) {
            int idx = sh_base[1] + w2o + __popc(m2 & lt);
            g_q2[idx * 2]     = make_float4(__int_as_float(n), __int_as_float(camA | (camB << 8)), xsA, ysA);
            g_q2[idx * 2 + 1] = make_float4(xsB, ysB, z0, z1);
        }
    }
}

__device__ __forceinline__ float2 bilin(int cam, float xs, float ys, int lane) {
    float x0 = floorf(xs), y0 = floorf(ys);
    float wx1 = xs - x0, wx0 = 1.f - wx1;
    float wy1 = ys - y0, wy0 = 1.f - wy1;
    float ax = 0.f, ay = 0.f;
    const float2* base = (const float2*)(g_featT + (size_t)cam * HWp * CF);
#pragma unroll
    for (int corner = 0; corner < 4; corner++) {
        float xi = x0 + (float)(corner & 1);
        float yi = y0 + (float)(corner >> 1);
        if (xi >= 0.f && xi <= 159.f && yi >= 0.f && yi <= 87.f) {
            float w = ((corner & 1) ? wx1 : wx0) * ((corner >> 1) ? wy1 : wy0);
            int pixi = (int)yi * Ww + (int)xi;
            float2 v = __ldg(base + pixi * 32 + lane);
            ax += w * v.x;
            ay += w * v.y;
        }
    }
    return make_float2(ax, ay);
}

// body shared by gemm65 and combo: stage weights once, grid-stride over tiles.
// Gather batched 2-wide (four rounds) to cap live prefetch registers.
template<int KR, int QIDX>
__device__ __forceinline__ void gemm_tiles(float* smem, const float* __restrict__ bias,
                                           float* __restrict__ out, int total)
{
    float2* w2  = (float2*)smem;                 // [KR][32]
    float*  fsm = smem + KR * 64;                // [KR][68] feats / sout alias
    float*  sb  = fsm + KR * 68;                 // [64]
    int*    s_n = (int*)(sb + 64);               // [64]

    int tid = threadIdx.x, lane = tid & 31, warp = tid >> 5;
    const float2* Wp = QIDX ? g_w2p : g_w1p;
    for (int i = tid; i < KR * 32; i += 256)     // coalesced packed copy
        w2[i] = __ldg(Wp + i);
    if (tid < 64) sb[tid] = bias[tid];

    const float4* q = QIDX ? g_q2 : g_q1;
    for (int tile = blockIdx.x; tile * 64 < total; tile += gridDim.x) {
        __syncthreads();
        // ---- gather: four rounds of 2-wide record prefetch + bilinears ----
#pragma unroll
        for (int jb = 0; jb < 4; jb++) {
            float4 ra[2], rb[2];
#pragma unroll
            for (int u = 0; u < 2; u++) {
                int r = tile * 64 + warp * 8 + jb * 2 + u;
                if (r < total) {
                    ra[u] = __ldg(q + r * 2);
                    rb[u] = __ldg(q + r * 2 + 1);
                } else {
                    ra[u] = make_float4(__int_as_float(-1), 0.f, 0.f, 0.f);
                    rb[u] = make_float4(0.f, 0.f, 0.f, 0.f);
                }
            }
#pragma unroll
            for (int u = 0; u < 2; u++) {
                int v = warp * 8 + jb * 2 + u;
                int n = __float_as_int(ra[u].x);
                if (n >= 0) {
                    if (QIDX == 0) {
                        int cam = __float_as_int(ra[u].y);
                        float2 a = bilin(cam, ra[u].z, ra[u].w, lane);
                        fsm[(2 * lane) * 68 + v]     = a.x;
                        fsm[(2 * lane + 1) * 68 + v] = a.y;
                        if (lane == 0) { fsm[64 * 68 + v] = rb[u].x; s_n[v] = n; }
                    } else {
                        int cc = __float_as_int(ra[u].y);
                        int camA = cc & 255, camB = cc >> 8;
                        float2 a = bilin(camA, ra[u].z, ra[u].w, lane);
                        float2 b = bilin(camB, rb[u].x, rb[u].y, lane);
                        float2 h0 = make_float2(0.f, 0.f), h1 = make_float2(0.f, 0.f);
                        if (camA == 0 || camA == 3 || camA == 4) { h0.x += a.x; h0.y += a.y; }
                        else                                     { h1.x += a.x; h1.y += a.y; }
                        if (camB == 0 || camB == 3 || camB == 4) { h0.x += b.x; h0.y += b.y; }
                        else                                     { h1.x += b.x; h1.y += b.y; }
                        fsm[(2 * lane) * 68 + v]          = h0.x;
                        fsm[(2 * lane + 1) * 68 + v]      = h0.y;
                        fsm[(65 + 2 * lane) * 68 + v]     = h1.x;
                        fsm[(65 + 2 * lane + 1) * 68 + v] = h1.y;
                        if (lane == 0) { fsm[64 * 68 + v] = rb[u].z; fsm[129 * 68 + v] = rb[u].w; s_n[v] = n; }
                    }
                } else if (lane == 0) s_n[v] = -1;
            }
        }
        __syncthreads();
        // ---- GEMM ----
        float acc[16];
#pragma unroll
        for (int i = 0; i < 16; i++) acc[i] = 0.f;
        int vb = warp * 8;
#pragma unroll 5
        for (int k = 0; k < KR; k++) {
            float2 wv = w2[k * 32 + lane];
            float4 f0 = *(const float4*)(fsm + k * 68 + vb);
            float4 f1 = *(const float4*)(fsm + k * 68 + vb + 4);
            acc[0]  = fmaf(wv.x, f0.x, acc[0]);  acc[1]  = fmaf(wv.y, f0.x, acc[1]);
            acc[2]  = fmaf(wv.x, f0.y, acc[2]);  acc[3]  = fmaf(wv.y, f0.y, acc[3]);
            acc[4]  = fmaf(wv.x, f0.z, acc[4]);  acc[5]  = fmaf(wv.y, f0.z, acc[5]);
            acc[6]  = fmaf(wv.x, f0.w, acc[6]);  acc[7]  = fmaf(wv.y, f0.w, acc[7]);
            acc[8]  = fmaf(wv.x, f1.x, acc[8]);  acc[9]  = fmaf(wv.y, f1.x, acc[9]);
            acc[10] = fmaf(wv.x, f1.y, acc[10]); acc[11] = fmaf(wv.y, f1.y, acc[11]);
            acc[12] = fmaf(wv.x, f1.z, acc[12]); acc[13] = fmaf(wv.y, f1.z, acc[13]);
            acc[14] = fmaf(wv.x, f1.w, acc[14]); acc[15] = fmaf(wv.y, f1.w, acc[15]);
        }
        __syncthreads();
        float* som = fsm;
        float b0 = sb[lane], b1 = sb[lane + 32];
#pragma unroll
        for (int j = 0; j < 8; j++) {
            som[lane * 65 + vb + j]        = elu1(acc[2 * j]     + b0);
            som[(lane + 32) * 65 + vb + j] = elu1(acc[2 * j + 1] + b1);
        }
        __syncthreads();
#pragma unroll
        for (int i = tid; i < 64 * 64; i += 256) {
            int o = i >> 6, v = i & 63;
            int nn = s_n[v];
            if (nn >= 0) out[(size_t)o * NVOX + nn] = som[o * 65 + v];
        }
    }
}

__global__ __launch_bounds__(256, 5) void gemm65_kernel(
    const float* __restrict__ bias, float* __restrict__ out)
{
    extern __shared__ float smem[];
    int total = g_cnt[0];
    if (blockIdx.x * 64 >= total) return;
    gemm_tiles<65, 0>(smem, bias, out, total);
}

// combo: q2 GEMM tiles + zero-fill of inactive columns, one launch
__global__ __launch_bounds__(256) void combo_kernel(
    const float* __restrict__ bias, float* __restrict__ out)
{
    extern __shared__ float smem[];
    int total = g_cnt[1];
    if (blockIdx.x * 64 < total)
        gemm_tiles<130, 1>(smem, bias, out, total);
    // fill: every block handles one 256-voxel chunk
    int n = blockIdx.x * 256 + threadIdx.x;
    if (n < NVOX && !g_flag[n]) {
#pragma unroll
        for (int o = 0; o < 64; o++) out[(size_t)o * NVOX + n] = 0.f;
    }
}

extern "C" void kernel_launch(void* const* d_in, const int* in_sizes, int n_in,
                              void* d_out, int out_size) {
    const float* feat = (const float*)d_in[0];
    const float* mask = (const float*)d_in[1];
    const float* K    = (const float*)d_in[2];
    const float* ext  = (const float*)d_in[3];
    const float* w_no = (const float*)d_in[4];
    const float* b_no = (const float*)d_in[5];
    const float* w_o  = (const float*)d_in[6];
    const float* b_o  = (const float*)d_in[7];
    float* out = (float*)d_out;

    static cudaStream_t s1 = nullptr;
    static cudaEvent_t e0 = nullptr, e_t = nullptr, e_c = nullptr, e_f = nullptr;
    if (!s1) {
        cudaStreamCreateWithFlags(&s1, cudaStreamNonBlocking);
        cudaEventCreateWithFlags(&e0,  cudaEventDisableTiming);
        cudaEventCreateWithFlags(&e_t, cudaEventDisableTiming);
        cudaEventCreateWithFlags(&e_c, cudaEventDisableTiming);
        cudaEventCreateWithFlags(&e_f, cudaEventDisableTiming);
    }

    const int smem1 = (65 * 64  + 65 * 68  + 64 + 64) * 4;   // 34832
    const int smem2 = (130 * 64 + 130 * 68 + 64 + 64) * 4;   // 69152
    cudaFuncSetAttribute(gemm65_kernel, cudaFuncAttributeMaxDynamicSharedMemorySize, smem1);
    cudaFuncSetAttribute(combo_kernel,  cudaFuncAttributeMaxDynamicSharedMemorySize, smem2);

    // s0: pack(+cnt reset) -> classify -> [e_t] -> gemm65
    // s1: transpose -> [e_c] -> combo (q2 gemm + fill)
    cudaEventRecord(e0, 0);
    cudaStreamWaitEvent(s1, e0, 0);

    dim3 tg(HWp / 32, CF / 32, NC);   // 440 x 2 x 6
    transpose_kernel<<<tg, dim3(32, 8), 0, s1>>>(feat);
    cudaEventRecord(e_t, s1);

    pack_kernel<<<17, 256>>>(w_no, w_o);
    classify_kernel<<<(NVOX + 255) / 256, 256>>>(mask, K, ext);
    cudaEventRecord(e_c, 0);

    cudaStreamWaitEvent(0, e_t, 0);
    gemm65_kernel<<<888, 256, smem1, 0>>>(b_no, out);

    cudaStreamWaitEvent(s1, e_c, 0);
    combo_kernel<<<(NVOX + 255) / 256, 256, smem2, s1>>>(b_o, out);
    cudaEventRecord(e_f, s1);

    cudaStreamWaitEvent(0, e_f, 0);
}